// round 14
// baseline (speedup 1.0000x reference)
#include <cuda_runtime.h>
#include <cstdint>

// Problem constants (fixed shapes from reference setup_inputs)
#define B_   8
#define C_   4
#define N_   16
#define H_   256
#define W_   256
#define HW_  (H_ * W_)            // 65536
#define OPI_ (HW_ / 8)            // 8192 octs (8-pixel groups) per plane
#define TOTAL_OCTS (B_ * OPI_)    // 65536
#define BLOCK_ 256
#define GRID_  (TOTAL_OCTS / BLOCK_)        // 256 blocks, one oct per thread
#define DENOM ((double)B_ * N_ * C_ * HW_)  // 33554432

__device__ float        g_partial[GRID_];
__device__ unsigned int g_count = 0;   // wraps back to 0 every run via atomicInc

// 256-bit loads (sm_100+) with L1::no_allocate: every input line is touched
// exactly once by exactly one thread, so L1 allocation is pure overhead
// (dead fills + tag churn in the L1tex pipeline). Bypass it.
struct V8 { uint32_t r[8]; };
__device__ __forceinline__ V8 ldg256_na(const void* p) {
    V8 v;
    asm("ld.global.nc.L1::no_allocate.v8.b32 {%0,%1,%2,%3,%4,%5,%6,%7}, [%8];"
        : "=r"(v.r[0]), "=r"(v.r[1]), "=r"(v.r[2]), "=r"(v.r[3]),
          "=r"(v.r[4]), "=r"(v.r[5]), "=r"(v.r[6]), "=r"(v.r[7])
        : "l"(p));
    return v;
}

__global__ void __launch_bounds__(BLOCK_, 2)   // cap 128 regs -> 2 blocks/SM, single wave
mse_fused_kernel(const float* __restrict__ pd,
                 const float* __restrict__ gt,
                 const int*   __restrict__ pdm,   // bool upconverted to int32 (0/1)
                 const int*   __restrict__ gtm,
                 float*       __restrict__ out)
{
    const int t  = blockIdx.x * BLOCK_ + threadIdx.x;   // one oct per thread
    const int b  = t >> 13;               // t / OPI_
    const int p8 = (t & (OPI_ - 1)) << 3; // pixel offset within the HxW plane

    // ---- Mask popcounts over N=16 slots, 8 pixels per thread ----
    const long mbase = (long)b * N_ * HW_ + p8;
    int sp[8] = {0,0,0,0,0,0,0,0};
    int sg[8] = {0,0,0,0,0,0,0,0};
    int sb[8] = {0,0,0,0,0,0,0,0};
    #pragma unroll
    for (int n = 0; n < N_; n++) {
        V8 mp = ldg256_na(pdm + mbase + (long)n * HW_);
        V8 mg = ldg256_na(gtm + mbase + (long)n * HW_);
        #pragma unroll
        for (int i = 0; i < 8; i++) {
            sp[i] += (int)mp.r[i];
            sg[i] += (int)mg.r[i];
            sb[i] += (int)(mp.r[i] & mg.r[i]);
        }
    }

    // ---- pd/gt channel reductions: P = sum pd^2, G = sum gt^2, X = sum pd*gt ----
    float P[8] = {0,0,0,0,0,0,0,0};
    float G[8] = {0,0,0,0,0,0,0,0};
    float X[8] = {0,0,0,0,0,0,0,0};
    #pragma unroll
    for (int c = 0; c < C_; c++) {
        long off = (long)(b * C_ + c) * HW_ + p8;
        V8 av = ldg256_na(pd + off);
        V8 gv = ldg256_na(gt + off);
        #pragma unroll
        for (int i = 0; i < 8; i++) {
            float a = __uint_as_float(av.r[i]);
            float g = __uint_as_float(gv.r[i]);
            P[i] = fmaf(a, a, P[i]);
            G[i] = fmaf(g, g, G[i]);
            X[i] = fmaf(a, g, X[i]);
        }
    }

    // ---- Combine: np*P + ng*G - 2*npg*X per pixel ----
    float local = 0.0f;
    #pragma unroll
    for (int i = 0; i < 8; i++)
        local += (float)sp[i] * P[i] + (float)sg[i] * G[i]
               - 2.0f * (float)sb[i] * X[i];

    // ---- Warp reduce, block reduce ----
    #pragma unroll
    for (int off = 16; off > 0; off >>= 1)
        local += __shfl_down_sync(0xFFFFFFFFu, local, off);

    __shared__ float warp_sums[8];   // 256 threads = 8 warps
    __shared__ bool  is_last;
    const int lane = threadIdx.x & 31;
    const int wid  = threadIdx.x >> 5;
    if (lane == 0) warp_sums[wid] = local;
    __syncthreads();

    if (wid == 0) {
        float v = (lane < 8) ? warp_sums[lane] : 0.0f;
        #pragma unroll
        for (int off = 4; off > 0; off >>= 1)
            v += __shfl_down_sync(0xFFFFFFFFu, v, off);
        if (lane == 0) {
            g_partial[blockIdx.x] = v;
            __threadfence();
            // atomicInc wraps: after the 256th block this returns GRID_-1 and
            // the counter is back at 0 -> deterministic across graph replays.
            unsigned int old = atomicInc(&g_count, GRID_ - 1);
            is_last = (old == GRID_ - 1);
        }
    }
    __syncthreads();

    // ---- Last block: reduce the 256 partials in double, write result ----
    if (is_last) {
        double dv = (double)__ldcg(&g_partial[threadIdx.x]);
        #pragma unroll
        for (int off = 16; off > 0; off >>= 1)
            dv += __shfl_down_sync(0xFFFFFFFFu, dv, off);

        __shared__ double dws[8];
        if (lane == 0) dws[wid] = dv;
        __syncthreads();
        if (wid == 0) {
            double s = (lane < 8) ? dws[lane] : 0.0;
            #pragma unroll
            for (int off = 4; off > 0; off >>= 1)
                s += __shfl_down_sync(0xFFFFFFFFu, s, off);
            if (lane == 0)
                out[0] = (float)(s / DENOM);
        }
    }
}

extern "C" void kernel_launch(void* const* d_in, const int* in_sizes, int n_in,
                              void* d_out, int out_size)
{
    const float* pd  = (const float*)d_in[0];
    const float* gt  = (const float*)d_in[1];
    const int*   pdm = (const int*)d_in[2];
    const int*   gtm = (const int*)d_in[3];
    float* out = (float*)d_out;

    mse_fused_kernel<<<GRID_, BLOCK_>>>(pd, gt, pdm, gtm, out);
}

// round 15
// speedup vs baseline: 1.0204x; 1.0204x over previous
#include <cuda_runtime.h>
#include <cstdint>

// Problem constants (fixed shapes from reference setup_inputs)
#define B_   8
#define C_   4
#define N_   16
#define H_   256
#define W_   256
#define HW_  (H_ * W_)            // 65536
#define OPI_ (HW_ / 8)            // 8192 octs (8-pixel groups) per plane
#define TOTAL_OCTS (B_ * OPI_)    // 65536
#define BLOCK_ 256
#define GRID_  (TOTAL_OCTS / BLOCK_)        // 256 blocks, one oct per thread
#define DENOM ((double)B_ * N_ * C_ * HW_)  // 33554432

__device__ float        g_partial[GRID_];
__device__ unsigned int g_count = 0;   // wraps back to 0 every run via atomicInc

// 256-bit loads (sm_100+): half the LDG count of float4/int4 for the same
// bytes -> half the LSU dispatch cycles and 2x bytes per outstanding-load slot.
struct V8 { uint32_t r[8]; };
__device__ __forceinline__ V8 ldg256(const void* p) {
    V8 v;
    asm("ld.global.nc.v8.b32 {%0,%1,%2,%3,%4,%5,%6,%7}, [%8];"
        : "=r"(v.r[0]), "=r"(v.r[1]), "=r"(v.r[2]), "=r"(v.r[3]),
          "=r"(v.r[4]), "=r"(v.r[5]), "=r"(v.r[6]), "=r"(v.r[7])
        : "l"(p));
    return v;
}

__global__ void __launch_bounds__(BLOCK_, 2)   // cap 128 regs -> 2 blocks/SM, single wave
mse_fused_kernel(const float* __restrict__ pd,
                 const float* __restrict__ gt,
                 const int*   __restrict__ pdm,   // bool upconverted to int32 (0/1)
                 const int*   __restrict__ gtm,
                 float*       __restrict__ out)
{
    const int t  = blockIdx.x * BLOCK_ + threadIdx.x;   // one oct per thread
    const int b  = t >> 13;               // t / OPI_
    const int p8 = (t & (OPI_ - 1)) << 3; // pixel offset within the HxW plane

    // ---- Mask popcounts over N=16 slots, 8 pixels per thread ----
    const long mbase = (long)b * N_ * HW_ + p8;
    int sp[8] = {0,0,0,0,0,0,0,0};
    int sg[8] = {0,0,0,0,0,0,0,0};
    int sb[8] = {0,0,0,0,0,0,0,0};
    #pragma unroll
    for (int n = 0; n < N_; n++) {
        V8 mp = ldg256(pdm + mbase + (long)n * HW_);
        V8 mg = ldg256(gtm + mbase + (long)n * HW_);
        #pragma unroll
        for (int i = 0; i < 8; i++) {
            sp[i] += (int)mp.r[i];
            sg[i] += (int)mg.r[i];
            sb[i] += (int)(mp.r[i] & mg.r[i]);
        }
    }

    // ---- pd/gt channel reductions: P = sum pd^2, G = sum gt^2, X = sum pd*gt ----
    float P[8] = {0,0,0,0,0,0,0,0};
    float G[8] = {0,0,0,0,0,0,0,0};
    float X[8] = {0,0,0,0,0,0,0,0};
    #pragma unroll
    for (int c = 0; c < C_; c++) {
        long off = (long)(b * C_ + c) * HW_ + p8;
        V8 av = ldg256(pd + off);
        V8 gv = ldg256(gt + off);
        #pragma unroll
        for (int i = 0; i < 8; i++) {
            float a = __uint_as_float(av.r[i]);
            float g = __uint_as_float(gv.r[i]);
            P[i] = fmaf(a, a, P[i]);
            G[i] = fmaf(g, g, G[i]);
            X[i] = fmaf(a, g, X[i]);
        }
    }

    // ---- Combine: np*P + ng*G - 2*npg*X per pixel ----
    float local = 0.0f;
    #pragma unroll
    for (int i = 0; i < 8; i++)
        local += (float)sp[i] * P[i] + (float)sg[i] * G[i]
               - 2.0f * (float)sb[i] * X[i];

    // ---- Warp reduce, block reduce ----
    #pragma unroll
    for (int off = 16; off > 0; off >>= 1)
        local += __shfl_down_sync(0xFFFFFFFFu, local, off);

    __shared__ float warp_sums[8];   // 256 threads = 8 warps
    __shared__ bool  is_last;
    const int lane = threadIdx.x & 31;
    const int wid  = threadIdx.x >> 5;
    if (lane == 0) warp_sums[wid] = local;
    __syncthreads();

    if (wid == 0) {
        float v = (lane < 8) ? warp_sums[lane] : 0.0f;
        #pragma unroll
        for (int off = 4; off > 0; off >>= 1)
            v += __shfl_down_sync(0xFFFFFFFFu, v, off);
        if (lane == 0) {
            g_partial[blockIdx.x] = v;
            __threadfence();
            // atomicInc wraps: after the 256th block this returns GRID_-1 and
            // the counter is back at 0 -> deterministic across graph replays.
            unsigned int old = atomicInc(&g_count, GRID_ - 1);
            is_last = (old == GRID_ - 1);
        }
    }
    __syncthreads();

    // ---- Last block: reduce the 256 partials in double, write result ----
    if (is_last) {
        double dv = (double)__ldcg(&g_partial[threadIdx.x]);
        #pragma unroll
        for (int off = 16; off > 0; off >>= 1)
            dv += __shfl_down_sync(0xFFFFFFFFu, dv, off);

        __shared__ double dws[8];
        if (lane == 0) dws[wid] = dv;
        __syncthreads();
        if (wid == 0) {
            double s = (lane < 8) ? dws[lane] : 0.0;
            #pragma unroll
            for (int off = 4; off > 0; off >>= 1)
                s += __shfl_down_sync(0xFFFFFFFFu, s, off);
            if (lane == 0)
                out[0] = (float)(s / DENOM);
        }
    }
}

extern "C" void kernel_launch(void* const* d_in, const int* in_sizes, int n_in,
                              void* d_out, int out_size)
{
    const float* pd  = (const float*)d_in[0];
    const float* gt  = (const float*)d_in[1];
    const int*   pdm = (const int*)d_in[2];
    const int*   gtm = (const int*)d_in[3];
    float* out = (float*)d_out;

    mse_fused_kernel<<<GRID_, BLOCK_>>>(pd, gt, pdm, gtm, out);
}